// round 10
// baseline (speedup 1.0000x reference)
#include <cuda_runtime.h>
#include <stdint.h>
#include <math.h>

#define B    8
#define C    64
#define T    4096
#define KNN  9
#define INVS (1.0f/16129.0f)

typedef unsigned long long u64;
typedef unsigned int       u32;

// Scratch (allocation-free: __device__ globals)
__device__ float g_qT[B * T * C];      // normalized q fp32 [b][t][c]
__device__ float g_kT[B * T * C];      // normalized k fp32
__device__ float g_vT[B * T * C];      // v fp32
__device__ u32   g_q8[B * T * 16];     // int8-packed normalized q
__device__ u32   g_k8[B * T * 16];     // int8-packed normalized k
__device__ float g_eq[B * T];          // ||q - q8/127|| (inflated, rigorous)
__device__ float g_ek[B * T];          // ||k - k8/127||
__device__ float g_wP[KNN * C * C];    // conv_w permuted [kk][cc][o]
__device__ int   g_idx[B * T * KNN];   // top-9 indices per (b,i)

// ---------------------------------------------------------------------------
__device__ __forceinline__ u64 pk2(float lo, float hi) {
    u64 r; asm("mov.b64 %0, {%1, %2};" : "=l"(r) : "f"(lo), "f"(hi)); return r;
}
__device__ __forceinline__ u64 fma2(u64 a, u64 b, u64 c) {
    u64 d; asm("fma.rn.f32x2 %0, %1, %2, %3;" : "=l"(d) : "l"(a), "l"(b), "l"(c));
    return d;
}
__device__ __forceinline__ void unpk(u64 v, float& lo, float& hi) {
    asm("mov.b64 {%0, %1}, %2;" : "=f"(lo), "=f"(hi) : "l"(v));
}

// Lex Top9: value desc, index asc on ties (== jax top_k). Any insert order.
struct Top9 {
    float v0,v1,v2,v3,v4,v5,v6,v7,v8;
    int   j0,j1,j2,j3,j4,j5,j6,j7,j8;
    __device__ __forceinline__ void init() {
        v0=v1=v2=v3=v4=v5=v6=v7=v8 = -1.f;
        j0=j1=j2=j3=j4=j5=j6=j7=j8 = 0x7FFFFFFF;
    }
    __device__ __forceinline__ void insert(float s, int j) {
        if ((s > v8) || (s == v8 && j < j8)) {
            v8 = s; j8 = j;
            #define _LSW(va,ja,vb,jb) if (((vb) > (va)) || ((vb) == (va) && (jb) < (ja))) { \
                float tv=(va); (va)=(vb); (vb)=tv; int tj=(ja); (ja)=(jb); (jb)=tj; }
            _LSW(v7,j7,v8,j8); _LSW(v6,j6,v7,j7); _LSW(v5,j5,v6,j6);
            _LSW(v4,j4,v5,j5); _LSW(v3,j3,v4,j4); _LSW(v2,j2,v3,j3);
            _LSW(v1,j1,v2,j2); _LSW(v0,j0,v1,j1);
            #undef _LSW
        }
    }
    __device__ __forceinline__ void store(int* op) {
        op[0]=j0; op[1]=j1; op[2]=j2; op[3]=j3; op[4]=j4;
        op[5]=j5; op[6]=j6; op[7]=j7; op[8]=j8;
    }
};

// exact sequential-chain dot (bitwise reference ranking; validated R3/R8)
__device__ float exact_dot(const float* kr, const float* __restrict__ qrow)
{
    float s = 0.f;
    for (int c4 = 0; c4 < 16; c4++) {
        float4 q = __ldg((const float4*)qrow + c4);
        s = __fmaf_rn(kr[4*c4+0], q.x, s);
        s = __fmaf_rn(kr[4*c4+1], q.y, s);
        s = __fmaf_rn(kr[4*c4+2], q.z, s);
        s = __fmaf_rn(kr[4*c4+3], q.w, s);
    }
    return s;
}

#define INS32(key) do { u32 k_ = (key);                                       \
    if (k_ > lst[31]) { lst[31] = k_;                                         \
        _Pragma("unroll")                                                     \
        for (int z_ = 30; z_ >= 0; z_--) {                                    \
            if (lst[z_+1] > lst[z_]) { u32 t_ = lst[z_]; lst[z_] = lst[z_+1]; lst[z_+1] = t_; } \
            else break; } } } while (0)

// ---------------------------------------------------------------------------
__global__ void permute_w_kernel(const float* __restrict__ conv_w) {
    int s = blockIdx.x * 256 + threadIdx.x;
    if (s < KNN * C * C) {
        int o  = s & 63;
        int cc = (s >> 6) & 63;
        int kk = s >> 12;
        g_wP[s] = conv_w[o * (C * KNN) + cc * KNN + kk];
    }
}

// ---------------------------------------------------------------------------
// Kernel 1: projections + L2 normalize; fp32 out + int8 pack + residual norms
// ---------------------------------------------------------------------------
__global__ __launch_bounds__(128) void proj_kernel(
    const float* __restrict__ x,
    const float* __restrict__ Wq,
    const float* __restrict__ Wk,
    const float* __restrict__ Wv)
{
    __shared__ float Xs[C][128];
    __shared__ float Ws[C][C];

    const int b   = blockIdx.y;
    const int t0  = blockIdx.x * 128;
    const int tid = threadIdx.x;

    const float* xb = x + (size_t)b * C * T;
    for (int c = 0; c < C; c++)
        Xs[c][tid] = xb[c * T + t0 + tid];

    for (int m = 0; m < 3; m++) {
        const float* W = (m == 0) ? Wq : ((m == 1) ? Wk : Wv);
        float* dstbase = (m == 0) ? g_qT : ((m == 1) ? g_kT : g_vT);

        __syncthreads();
        for (int s = tid; s < C * C; s += 128) {
            int c = s >> 6, d = s & 63;
            Ws[c][d] = W[d * C + c];
        }
        __syncthreads();

        float acc[C];
        #pragma unroll
        for (int d = 0; d < C; d++) acc[d] = 0.f;

        for (int c = 0; c < C; c++) {
            float xv = Xs[c][tid];
            const float4* wr = (const float4*)Ws[c];
            #pragma unroll
            for (int d4 = 0; d4 < 16; d4++) {
                float4 w = wr[d4];
                acc[4*d4+0] = __fmaf_rn(w.x, xv, acc[4*d4+0]);
                acc[4*d4+1] = __fmaf_rn(w.y, xv, acc[4*d4+1]);
                acc[4*d4+2] = __fmaf_rn(w.z, xv, acc[4*d4+2]);
                acc[4*d4+3] = __fmaf_rn(w.w, xv, acc[4*d4+3]);
            }
        }

        if (m < 2) {
            float ss = 0.f;
            #pragma unroll
            for (int d = 0; d < C; d++)
                ss = __fadd_rn(ss, __fmul_rn(acc[d], acc[d]));
            float n = fmaxf(sqrtf(ss), 1e-12f);
            #pragma unroll
            for (int d = 0; d < C; d++)
                acc[d] = __fdiv_rn(acc[d], n);
        }

        float4* dst = (float4*)(dstbase + ((size_t)b * T + t0 + tid) * C);
        #pragma unroll
        for (int d4 = 0; d4 < 16; d4++)
            dst[d4] = make_float4(acc[4*d4+0], acc[4*d4+1], acc[4*d4+2], acc[4*d4+3]);

        if (m < 2) {   // int8 quantize + pack + rigorous residual norm
            u32 pk[16];
            float errss = 0.f;
            #pragma unroll
            for (int wi = 0; wi < 16; wi++) {
                u32 word = 0;
                #pragma unroll
                for (int e = 0; e < 4; e++) {
                    int   c  = wi * 4 + e;
                    int   qi = __float2int_rn(acc[c] * 127.f);
                    float dq = __fmaf_rn((float)(-qi), 0.007874015748031496f, acc[c]);
                    errss = __fmaf_rn(dq, dq, errss);
                    word |= ((u32)qi & 0xFFu) << (8 * e);
                }
                pk[wi] = word;
            }
            float ev = sqrtf(errss) * 1.02f + 1e-6f;
            u32* d8 = ((m == 0) ? g_q8 : g_k8) + ((size_t)b * T + t0 + tid) * 16;
            #pragma unroll
            for (int wi = 0; wi < 4; wi++)
                *(uint4*)(d8 + wi * 4) = *(uint4*)(pk + wi * 4);
            if (m == 0) g_eq[(size_t)b * T + t0 + tid] = ev;
            else        g_ek[(size_t)b * T + t0 + tid] = ev;
        }
    }
}

// ---------------------------------------------------------------------------
// Kernel 2: dp4a int8 prefilter (thread-per-row, top-32) -> exact fp32
//           re-rank -> lex Top9; sound per-row bound; warp-coop tier-2.
// ---------------------------------------------------------------------------
__global__ __launch_bounds__(256) void sim_topk_kernel()
{
    __shared__ u32   Q8s[256 * 20];    // staged q8 tile, stride 20 (16B-aligned)
    __shared__ float EQs[256];
    __shared__ int   t2cnt[8];
    __shared__ int   t2lst[8][96];

    const int    b   = blockIdx.y;
    const int    tid = threadIdx.x;
    const int    i   = blockIdx.x * 256 + tid;
    const size_t bT  = (size_t)b * T;

    u32 k8[16];
    {
        const uint4* kp = (const uint4*)(g_q8 + 0);  // placeholder silence
        kp = (const uint4*)(g_k8 + (bT + i) * 16);
        #pragma unroll
        for (int w4 = 0; w4 < 4; w4++) {
            uint4 v = __ldg(kp + w4);
            k8[w4*4+0] = v.x; k8[w4*4+1] = v.y; k8[w4*4+2] = v.z; k8[w4*4+3] = v.w;
        }
    }
    const float Ep = __fmaf_rn(1.04f, __ldg(&g_ek[bT + i]), 1e-3f);

    u32 lst[32];
    #pragma unroll
    for (int m = 0; m < 32; m++) lst[m] = 0u;

    for (int jt = 0; jt < T; jt += 256) {
        __syncthreads();
        {
            const uint4* src = (const uint4*)(g_q8 + (bT + jt + tid) * 16);
            #pragma unroll
            for (int w4 = 0; w4 < 4; w4++)
                *(uint4*)&Q8s[tid * 20 + w4 * 4] = __ldg(src + w4);
            EQs[tid] = __ldg(&g_eq[bT + jt + tid]);
        }
        __syncthreads();

        for (int jj = 0; jj < 256; jj += 2) {
            const u32* qa = &Q8s[jj * 20];
            const u32* qb = &Q8s[(jj + 1) * 20];
            int a0=0,a1=0,a2=0,a3=0, c0=0,c1=0,c2=0,c3=0;
            #pragma unroll
            for (int t = 0; t < 4; t++) {
                uint4 va = *(const uint4*)(qa + t * 4);
                uint4 vb = *(const uint4*)(qb + t * 4);
                a0 = __dp4a((int)k8[t*4+0], (int)va.x, a0);
                a1 = __dp4a((int)k8[t*4+1], (int)va.y, a1);
                a2 = __dp4a((int)k8[t*4+2], (int)va.z, a2);
                a3 = __dp4a((int)k8[t*4+3], (int)va.w, a3);
                c0 = __dp4a((int)k8[t*4+0], (int)vb.x, c0);
                c1 = __dp4a((int)k8[t*4+1], (int)vb.y, c1);
                c2 = __dp4a((int)k8[t*4+2], (int)vb.z, c2);
                c3 = __dp4a((int)k8[t*4+3], (int)vb.w, c3);
            }
            int  sa = (a0 + a1) + (a2 + a3);
            int  sb = (c0 + c1) + (c2 + c3);
            float fa = __fmaf_rn((float)(sa > 0 ? sa : 0), INVS, EQs[jj]);
            float fb = __fmaf_rn((float)(sb > 0 ? sb : 0), INVS, EQs[jj + 1]);
            u32 ka = (__float_as_uint(fa) & 0xFFFFF000u) | (u32)(4095 - (jt + jj));
            u32 kb = (__float_as_uint(fb) & 0xFFFFF000u) | (u32)(4095 - (jt + jj + 1));
            INS32(ka);
            INS32(kb);
        }
    }

    // exact fp32 k row (local-addressable for looped dots)
    float kr[C];
    {
        const float4* kp4 = (const float4*)(g_kT + (bT + i) * C);
        #pragma unroll
        for (int c4 = 0; c4 < 16; c4++) {
            float4 v = __ldg(kp4 + c4);
            kr[4*c4+0] = v.x; kr[4*c4+1] = v.y; kr[4*c4+2] = v.z; kr[4*c4+3] = v.w;
        }
    }

    // copy shortlist to a dynamically-indexable array (lst stays in regs)
    u32 tmp[32];
    #pragma unroll
    for (int m = 0; m < 32; m++) tmp[m] = lst[m];

    Top9 t9;
    t9.init();
    for (int m = 0; m < 32; m++) {
        int j = 4095 - (int)(tmp[m] & 0xFFFu);
        float s = exact_dot(kr, g_qT + (bT + j) * C);
        t9.insert(fmaxf(s, 0.f), j);
    }
    float v9c = t9.v8;

    // sound coverage check: excluded j have s_cl <= cutU + Ep
    float cutU = __uint_as_float((((lst[31] >> 12) + 2u) << 12));
    int   flag = (cutU + Ep >= v9c) ? 1 : 0;

    // ---- tier-2: warp-cooperative threshold re-sweep for flagged rows ----
    const unsigned fm = 0xffffffffu;
    const int w = tid >> 5, lane = tid & 31;
    unsigned bal = __ballot_sync(fm, flag);
    while (bal) {
        int r = __ffs(bal) - 1;
        bal &= bal - 1;
        u32 kb8[16];
        #pragma unroll
        for (int t = 0; t < 16; t++) kb8[t] = __shfl_sync(fm, k8[t], r);
        float theta = __shfl_sync(fm, v9c, r) - __shfl_sync(fm, Ep, r);
        if (lane == 0) t2cnt[w] = 0;
        __syncwarp();
        for (int j = lane; j < T; j += 32) {
            const uint4* qp = (const uint4*)(g_q8 + (bT + j) * 16);
            int d0=0,d1=0,d2=0,d3=0;
            #pragma unroll
            for (int t = 0; t < 4; t++) {
                uint4 v = __ldg(qp + t);
                d0 = __dp4a((int)kb8[t*4+0], (int)v.x, d0);
                d1 = __dp4a((int)kb8[t*4+1], (int)v.y, d1);
                d2 = __dp4a((int)kb8[t*4+2], (int)v.z, d2);
                d3 = __dp4a((int)kb8[t*4+3], (int)v.w, d3);
            }
            int   sv = (d0 + d1) + (d2 + d3);
            float sh = __fmaf_rn((float)(sv > 0 ? sv : 0), INVS, __ldg(&g_eq[bT + j]));
            if (sh >= theta) {
                int p = atomicAdd(&t2cnt[w], 1);
                if (p < 96) t2lst[w][p] = j;
            }
        }
        __syncwarp();
        if (lane == r) {
            int n = t2cnt[w];
            t9.init();
            if (n > 96) {   // ultimate fallback: full exact scan
                for (int j = 0; j < T; j++) {
                    float s = exact_dot(kr, g_qT + (bT + j) * C);
                    t9.insert(fmaxf(s, 0.f), j);
                }
            } else {
                for (int e = 0; e < n; e++) {
                    int j = t2lst[w][e];
                    float s = exact_dot(kr, g_qT + (bT + j) * C);
                    t9.insert(fmaxf(s, 0.f), j);
                }
            }
        }
        __syncwarp();
    }

    t9.store(g_idx + (bT + i) * KNN);
}

// ---------------------------------------------------------------------------
// Kernel 3: gather v + 1x1 conv (576 -> 64) + bias (R4 version, 92us)
// ---------------------------------------------------------------------------
__global__ __launch_bounds__(128) void gather_conv_kernel(
    const float* __restrict__ conv_b,
    float* __restrict__ out)
{
    __shared__ float  Ws[C * C];
    __shared__ float4 Vs[4][16][33];

    const int b   = blockIdx.y;
    const int tid = threadIdx.x;
    const int w   = tid >> 5;
    const int l   = tid & 31;
    const int i   = blockIdx.x * 128 + tid;

    u64 accp[32];
    #pragma unroll
    for (int o2 = 0; o2 < 32; o2++) accp[o2] = 0ull;

    const int base = (b * T + i) * KNN;

    for (int kk = 0; kk < KNN; kk++) {
        __syncthreads();
        {
            const float4* wsrc = (const float4*)(g_wP + kk * C * C);
            float4* wdst = (float4*)Ws;
            #pragma unroll
            for (int r = 0; r < 8; r++)
                wdst[r * 128 + tid] = wsrc[r * 128 + tid];
        }

        int j = g_idx[base + kk];

        #pragma unroll
        for (int rp = 0; rp < 32; rp += 2) {
            int r  = rp + (l >> 4);
            int c4 = l & 15;
            int jr = __shfl_sync(0xffffffffu, j, r);
            float4 vv = ((const float4*)(g_vT + ((size_t)b * T + jr) * C))[c4];
            Vs[w][c4][r] = vv;
        }
        __syncthreads();

        #pragma unroll
        for (int c4 = 0; c4 < 16; c4++) {
            float4 xv = Vs[w][c4][l];
            float xs[4] = {xv.x, xv.y, xv.z, xv.w};
            #pragma unroll
            for (int e = 0; e < 4; e++) {
                u64 xd = pk2(xs[e], xs[e]);
                const ulonglong2* wr = (const ulonglong2*)(Ws + (c4 * 4 + e) * C);
                #pragma unroll
                for (int o4 = 0; o4 < 16; o4++) {
                    ulonglong2 wp = wr[o4];
                    accp[2*o4+0] = fma2(xd, wp.x, accp[2*o4+0]);
                    accp[2*o4+1] = fma2(xd, wp.y, accp[2*o4+1]);
                }
            }
        }
    }

    #pragma unroll
    for (int o2 = 0; o2 < 32; o2++) {
        float f0, f1;
        unpk(accp[o2], f0, f1);
        out[((size_t)(b * C + 2*o2 + 0)) * T + i] = f0 + __ldg(&conv_b[2*o2 + 0]);
        out[((size_t)(b * C + 2*o2 + 1)) * T + i] = f1 + __ldg(&conv_b[2*o2 + 1]);
    }
}

// ---------------------------------------------------------------------------
extern "C" void kernel_launch(void* const* d_in, const int* in_sizes, int n_in,
                              void* d_out, int out_size)
{
    const float* x      = (const float*)d_in[0];
    const float* Wq     = (const float*)d_in[1];
    const float* Wk     = (const float*)d_in[2];
    const float* Wv     = (const float*)d_in[3];
    const float* conv_w = (const float*)d_in[4];
    const float* conv_b = (const float*)d_in[5];
    float* out          = (float*)d_out;

    permute_w_kernel<<<(KNN * C * C + 255) / 256, 256>>>(conv_w);
    proj_kernel<<<dim3(T / 128, B), 128>>>(x, Wq, Wk, Wv);
    sim_topk_kernel<<<dim3(T / 256, B), 256>>>();
    gather_conv_kernel<<<dim3(T / 128, B), 128>>>(conv_b, out);
}